// round 1
// baseline (speedup 1.0000x reference)
#include <cuda_runtime.h>
#include <math.h>

typedef unsigned long long ull;

#define NB 65536
#define EDIM 256
#define ADIM 64
#define NHEADS 2
#define NK 16
#define SCALE 0.125f

// ---------------- scratch (device globals; no allocation APIs) ----------------
__device__ float g_Q[(size_t)NB * 128];        // [B, H*A]  32MB
__device__ float g_U[(size_t)NB * 512];        // [B, H*D] 128MB
__device__ float g_CTX[(size_t)NB * 512];      // [B, H*D] 128MB
__device__ float g_CONTEXT[(size_t)NB * 256];  // [B, D]    64MB
__device__ float g_WkT[2 * 256 * 64];          // Wk transposed: [h][c][a]
__device__ int   g_mask_mode;                  // 0=u8, 1=i32, 2=f32

// ---------------- packed fp32x2 helpers (sm_103a FFMA2) ----------------
__device__ __forceinline__ ull pack2(float lo, float hi) {
    ull v; asm("mov.b64 %0, {%1, %2};" : "=l"(v) : "f"(lo), "f"(hi)); return v;
}
__device__ __forceinline__ void unpack2(ull v, float& lo, float& hi) {
    asm("mov.b64 {%0, %1}, %2;" : "=f"(lo), "=f"(hi) : "l"(v));
}
#define FMA2(accv, av, bv) asm("fma.rn.f32x2 %0, %1, %2, %0;" : "+l"(accv) : "l"(av), "l"(bv))

// ---------------- valid_mask dtype probe ----------------
__global__ void k_detect_mask(const unsigned int* __restrict__ w) {
    if (threadIdx.x == 0 && blockIdx.x == 0) {
        int f32like = 1, i32like = 1;
        for (int i = 0; i < 64; i++) {
            unsigned v = w[i];
            if (v != 0u && v != 0x3F800000u) f32like = 0;
            if (v > 1u) i32like = 0;
        }
        g_mask_mode = f32like ? 2 : (i32like ? 1 : 0);
    }
}

__device__ __forceinline__ float maskval(const void* p, int b, int mode) {
    if (mode == 0) return ((const unsigned char*)p)[b] ? 1.0f : 0.0f;
    if (mode == 1) return ((const int*)p)[b] ? 1.0f : 0.0f;
    return (((const float*)p)[b] != 0.0f) ? 1.0f : 0.0f;
}

// ---------------- Wk transpose: WkT[h][c][a] = Wk[h][a][c] ----------------
__global__ void k_prep_wkt(const float* __restrict__ Wk) {
    int i = blockIdx.x * 256 + threadIdx.x;
    if (i < 2 * 64 * 256) {
        int h = i >> 14;
        int rem = i & 16383;
        int a = rem >> 8;
        int c = rem & 255;
        g_WkT[h * 16384 + c * 64 + a] = Wk[i];
    }
}

// ---------------- A-tile loader for GEMM (modes) ----------------
// AMODE 0: plain A[m*lda + k]
// AMODE 1: masked center (lda = 256)
// AMODE 2: concat [masked center | CONTEXT] (K = 512)
template <int AMODE>
__device__ __forceinline__ float4 load_a4(const float* __restrict__ A, int lda,
                                          int m, int k,
                                          const float* __restrict__ center,
                                          const void* __restrict__ maskp,
                                          const float* __restrict__ ctxin,
                                          int mmode) {
    if (AMODE == 0) {
        return *(const float4*)&A[(size_t)m * lda + k];
    } else if (AMODE == 1) {
        float4 v = *(const float4*)&center[(size_t)m * 256 + k];
        float f = maskval(maskp, m, mmode);
        v.x *= f; v.y *= f; v.z *= f; v.w *= f;
        return v;
    } else {
        if (k < 256) {
            float4 v = *(const float4*)&center[(size_t)m * 256 + k];
            float f = maskval(maskp, m, mmode);
            v.x *= f; v.y *= f; v.z *= f; v.w *= f;
            return v;
        } else {
            return *(const float4*)&ctxin[(size_t)m * 256 + (k - 256)];
        }
    }
}

__device__ __forceinline__ float gatemix(float x, float cv, float cx) {
    float g = 1.0f / (1.0f + expf(-x));
    return g * cv + (1.0f - g) * cx;
}

// ---------------- tiled fp32x2 GEMM: C[M,N] = A[M,K] @ Bw[N,K]^T ----------------
// BM=128, BN=64, BK=16, 256 threads, per-thread 8x4 outputs via 16 f32x2 accumulators.
template <int AMODE, int EPI>
__device__ __forceinline__ void gemm_body(const float* __restrict__ A, int lda,
                                          const float* __restrict__ Bw, int ldb,
                                          float* __restrict__ C, int ldc,
                                          int Kdim,
                                          const float* __restrict__ center,
                                          const void* __restrict__ maskp,
                                          const float* __restrict__ ctxin) {
    constexpr int BM = 128, BN = 64, BK = 16;
    __shared__ float As[BK][BM + 4];
    __shared__ float Bs[BK][BN];

    int t = threadIdx.x;
    int m0 = blockIdx.x * BM;
    int n0 = blockIdx.y * BN;
    int trow = (t >> 4) * 8;   // 0..120
    int tcol = (t & 15) * 4;   // 0..60

    int mmode = 0;
    if (AMODE != 0 || EPI == 1) mmode = g_mask_mode;

    ull acc[4][4];
#pragma unroll
    for (int p = 0; p < 4; p++)
#pragma unroll
        for (int j = 0; j < 4; j++) acc[p][j] = 0ull;

    int ar = t >> 2;          // 0..63
    int ak = (t & 3) * 4;     // 0,4,8,12
    int bn = t & 63;          // 0..63
    int bk = (t >> 6) * 4;    // 0,4,8,12

    for (int k0 = 0; k0 < Kdim; k0 += BK) {
        float4 v0 = load_a4<AMODE>(A, lda, m0 + ar, k0 + ak, center, maskp, ctxin, mmode);
        float4 v1 = load_a4<AMODE>(A, lda, m0 + ar + 64, k0 + ak, center, maskp, ctxin, mmode);
        As[ak + 0][ar] = v0.x; As[ak + 1][ar] = v0.y; As[ak + 2][ar] = v0.z; As[ak + 3][ar] = v0.w;
        As[ak + 0][ar + 64] = v1.x; As[ak + 1][ar + 64] = v1.y; As[ak + 2][ar + 64] = v1.z; As[ak + 3][ar + 64] = v1.w;

        float4 bv = *(const float4*)&Bw[(size_t)(n0 + bn) * ldb + k0 + bk];
        Bs[bk + 0][bn] = bv.x; Bs[bk + 1][bn] = bv.y; Bs[bk + 2][bn] = bv.z; Bs[bk + 3][bn] = bv.w;

        __syncthreads();
#pragma unroll
        for (int kk = 0; kk < BK; kk++) {
            ull a2[4];
#pragma unroll
            for (int p = 0; p < 4; p++)
                a2[p] = *(const ull*)&As[kk][trow + 2 * p];
            float4 b4 = *(const float4*)&Bs[kk][tcol];
            ull b2[4] = { pack2(b4.x, b4.x), pack2(b4.y, b4.y), pack2(b4.z, b4.z), pack2(b4.w, b4.w) };
#pragma unroll
            for (int p = 0; p < 4; p++)
#pragma unroll
                for (int j = 0; j < 4; j++)
                    FMA2(acc[p][j], a2[p], b2[j]);
        }
        __syncthreads();
    }

#pragma unroll
    for (int p = 0; p < 4; p++) {
        float lo[4], hi[4];
#pragma unroll
        for (int j = 0; j < 4; j++) unpack2(acc[p][j], lo[j], hi[j]);
        int r0 = m0 + trow + 2 * p;
        int cn = n0 + tcol;
        if (EPI == 0) {
            *(float4*)&C[(size_t)r0 * ldc + cn] = make_float4(lo[0], lo[1], lo[2], lo[3]);
            *(float4*)&C[(size_t)(r0 + 1) * ldc + cn] = make_float4(hi[0], hi[1], hi[2], hi[3]);
        } else {
            float fm0 = maskval(maskp, r0, mmode);
            float fm1 = maskval(maskp, r0 + 1, mmode);
            float4 cv0 = *(const float4*)&center[(size_t)r0 * 256 + cn];
            float4 cv1 = *(const float4*)&center[(size_t)(r0 + 1) * 256 + cn];
            float4 cx0 = *(const float4*)&ctxin[(size_t)r0 * 256 + cn];
            float4 cx1 = *(const float4*)&ctxin[(size_t)(r0 + 1) * 256 + cn];
            float4 o0, o1;
            o0.x = gatemix(lo[0], cv0.x * fm0, cx0.x);
            o0.y = gatemix(lo[1], cv0.y * fm0, cx0.y);
            o0.z = gatemix(lo[2], cv0.z * fm0, cx0.z);
            o0.w = gatemix(lo[3], cv0.w * fm0, cx0.w);
            o1.x = gatemix(hi[0], cv1.x * fm1, cx1.x);
            o1.y = gatemix(hi[1], cv1.y * fm1, cx1.y);
            o1.z = gatemix(hi[2], cv1.z * fm1, cx1.z);
            o1.w = gatemix(hi[3], cv1.w * fm1, cx1.w);
            *(float4*)&C[(size_t)r0 * ldc + cn] = o0;
            *(float4*)&C[(size_t)(r0 + 1) * ldc + cn] = o1;
        }
    }
}

// ---------------- GEMM entry kernels ----------------
__global__ void __launch_bounds__(256) k_gemm_q(const float* __restrict__ center,
                                                const float* __restrict__ Wq,
                                                const void* __restrict__ mask) {
    gemm_body<1, 0>(nullptr, 0, Wq, 256, g_Q, 128, 256, center, mask, nullptr);
}
__global__ void __launch_bounds__(256) k_gemm_u(int h) {
    gemm_body<0, 0>(g_Q + h * 64, 128, g_WkT + h * 16384, 64, g_U + h * 256, 512, 64,
                    nullptr, nullptr, nullptr);
}
__global__ void __launch_bounds__(256) k_gemm_ctx(const float* __restrict__ Wproj) {
    gemm_body<0, 0>(g_CTX, 512, Wproj, 512, g_CONTEXT, 256, 512, nullptr, nullptr, nullptr);
}
__global__ void __launch_bounds__(256) k_gemm_gate(const float* __restrict__ Wgate,
                                                   const float* __restrict__ center,
                                                   const void* __restrict__ mask,
                                                   float* __restrict__ out) {
    gemm_body<2, 1>(nullptr, 0, Wgate, 512, out, 256, 512, center, mask, g_CONTEXT);
}

// ---------------- attention: scores + softmax + context (DRAM-bound) ----------------
__global__ void __launch_bounds__(128) k_attn(const float* __restrict__ neigh,
                                              const float* __restrict__ conf) {
    __shared__ float sN[NK * 256];   // 16KB
    __shared__ float sU[512];
    __shared__ float sS[32];

    int b = blockIdx.x;
    int t = threadIdx.x;

    const float4* n4 = (const float4*)(neigh + (size_t)b * (NK * 256));
    float4* s4 = (float4*)sN;
#pragma unroll
    for (int i = 0; i < 8; i++) s4[t + i * 128] = n4[t + i * 128];
    ((float4*)sU)[t] = ((const float4*)(g_U + (size_t)b * 512))[t];
    __syncthreads();

    // scores: 32 (h,k) pairs, 4 lanes each
    {
        int p = t >> 2;
        int h = p >> 4;
        int k = p & 15;
        int l = t & 3;
        const float* u = sU + h * 256;
        const float* n = sN + k * 256;
        float s = 0.0f;
#pragma unroll 8
        for (int c = l; c < 256; c += 4) s += u[c] * n[c];
        s += __shfl_xor_sync(0xffffffffu, s, 1);
        s += __shfl_xor_sync(0xffffffffu, s, 2);
        if (l == 0) sS[p] = s * SCALE + logf(fmaxf(conf[(size_t)b * NK + k], 1e-8f));
    }
    __syncthreads();

    // softmax + ctx: thread t computes cols (t, t+128) for both heads
#pragma unroll
    for (int h = 0; h < 2; h++) {
        float m = -1e30f;
#pragma unroll
        for (int k = 0; k < NK; k++) m = fmaxf(m, sS[h * 16 + k]);
        float ws = 0.0f, c0 = 0.0f, c1 = 0.0f;
#pragma unroll
        for (int k = 0; k < NK; k++) {
            float w = expf(sS[h * 16 + k] - m);
            ws += w;
            c0 += w * sN[k * 256 + t];
            c1 += w * sN[k * 256 + t + 128];
        }
        float inv = 1.0f / ws;
        g_CTX[(size_t)b * 512 + h * 256 + t] = c0 * inv;
        g_CTX[(size_t)b * 512 + h * 256 + t + 128] = c1 * inv;
    }
}

// ---------------- launch ----------------
extern "C" void kernel_launch(void* const* d_in, const int* in_sizes, int n_in,
                              void* d_out, int out_size) {
    const float* center = (const float*)d_in[0];
    const float* neigh  = (const float*)d_in[1];
    const float* conf   = (const float*)d_in[2];
    const void*  mask   = d_in[3];
    const float* Wq     = (const float*)d_in[4];
    const float* Wk     = (const float*)d_in[5];
    const float* Wproj  = (const float*)d_in[6];
    const float* Wgate  = (const float*)d_in[7];
    float* out = (float*)d_out;

    k_detect_mask<<<1, 32>>>((const unsigned int*)mask);
    k_prep_wkt<<<128, 256>>>(Wk);

    k_gemm_q<<<dim3(NB / 128, 2), 256>>>(center, Wq, mask);
    k_gemm_u<<<dim3(NB / 128, 4), 256>>>(0);
    k_gemm_u<<<dim3(NB / 128, 4), 256>>>(1);

    k_attn<<<NB, 128>>>(neigh, conf);

    k_gemm_ctx<<<dim3(NB / 128, 4), 256>>>(Wproj);
    k_gemm_gate<<<dim3(NB / 128, 4), 256>>>(Wgate, center, mask, out);
}

// round 2
// speedup vs baseline: 1.0004x; 1.0004x over previous
#include <cuda_runtime.h>
#include <math.h>

typedef unsigned long long ull;

#define NB 65536
#define EDIM 256
#define ADIM 64
#define NHEADS 2
#define NK 16
#define SCALE 0.125f

// ---------------- scratch (device globals; no allocation APIs) ----------------
__device__ float g_Q[(size_t)NB * 128];        // [B, H*A]  32MB
__device__ float g_U[(size_t)NB * 512];        // [B, H*D] 128MB
__device__ float g_CTX[(size_t)NB * 512];      // [B, H*D] 128MB
__device__ float g_CONTEXT[(size_t)NB * 256];  // [B, D]    64MB
__device__ float g_WkT[2 * 256 * 64];          // Wk transposed: [h][c][a]
__device__ int   g_mask_mode;                  // 0=u8, 1=i32, 2=f32

// ---------------- packed fp32x2 helpers (sm_103a FFMA2) ----------------
__device__ __forceinline__ ull pack2(float lo, float hi) {
    ull v; asm("mov.b64 %0, {%1, %2};" : "=l"(v) : "f"(lo), "f"(hi)); return v;
}
__device__ __forceinline__ void unpack2(ull v, float& lo, float& hi) {
    asm("mov.b64 {%0, %1}, %2;" : "=f"(lo), "=f"(hi) : "l"(v));
}
#define FMA2(accv, av, bv) asm("fma.rn.f32x2 %0, %1, %2, %0;" : "+l"(accv) : "l"(av), "l"(bv))

// ---------------- valid_mask dtype probe ----------------
__global__ void k_detect_mask(const unsigned int* __restrict__ w) {
    if (threadIdx.x == 0 && blockIdx.x == 0) {
        int f32like = 1, i32like = 1;
        for (int i = 0; i < 64; i++) {
            unsigned v = w[i];
            if (v != 0u && v != 0x3F800000u) f32like = 0;
            if (v > 1u) i32like = 0;
        }
        g_mask_mode = f32like ? 2 : (i32like ? 1 : 0);
    }
}

__device__ __forceinline__ float maskval(const void* p, int b, int mode) {
    if (mode == 0) return ((const unsigned char*)p)[b] ? 1.0f : 0.0f;
    if (mode == 1) return ((const int*)p)[b] ? 1.0f : 0.0f;
    return (((const float*)p)[b] != 0.0f) ? 1.0f : 0.0f;
}

// ---------------- Wk transpose: WkT[h][c][a] = Wk[h][a][c] ----------------
__global__ void k_prep_wkt(const float* __restrict__ Wk) {
    int i = blockIdx.x * 256 + threadIdx.x;
    if (i < 2 * 64 * 256) {
        int h = i >> 14;
        int rem = i & 16383;
        int a = rem >> 8;
        int c = rem & 255;
        g_WkT[h * 16384 + c * 64 + a] = Wk[i];
    }
}

// ---------------- A-tile loader for GEMM (modes) ----------------
// AMODE 0: plain A[m*lda + k]
// AMODE 1: masked center (lda = 256)
// AMODE 2: concat [masked center | CONTEXT] (K = 512)
template <int AMODE>
__device__ __forceinline__ float4 load_a4(const float* __restrict__ A, int lda,
                                          int m, int k,
                                          const float* __restrict__ center,
                                          const void* __restrict__ maskp,
                                          const float* __restrict__ ctxin,
                                          int mmode) {
    if (AMODE == 0) {
        return *(const float4*)&A[(size_t)m * lda + k];
    } else if (AMODE == 1) {
        float4 v = *(const float4*)&center[(size_t)m * 256 + k];
        float f = maskval(maskp, m, mmode);
        v.x *= f; v.y *= f; v.z *= f; v.w *= f;
        return v;
    } else {
        if (k < 256) {
            float4 v = *(const float4*)&center[(size_t)m * 256 + k];
            float f = maskval(maskp, m, mmode);
            v.x *= f; v.y *= f; v.z *= f; v.w *= f;
            return v;
        } else {
            return *(const float4*)&ctxin[(size_t)m * 256 + (k - 256)];
        }
    }
}

__device__ __forceinline__ float gatemix(float x, float cv, float cx) {
    float g = 1.0f / (1.0f + expf(-x));
    return g * cv + (1.0f - g) * cx;
}

// ---------------- tiled fp32x2 GEMM: C[M,N] = A[M,K] @ Bw[N,K]^T ----------------
// BM=128, BN=64, BK=16, 256 threads, per-thread 8x4 outputs via 16 f32x2 accumulators.
template <int AMODE, int EPI>
__device__ __forceinline__ void gemm_body(const float* __restrict__ A, int lda,
                                          const float* __restrict__ Bw, int ldb,
                                          float* __restrict__ C, int ldc,
                                          int Kdim,
                                          const float* __restrict__ center,
                                          const void* __restrict__ maskp,
                                          const float* __restrict__ ctxin) {
    constexpr int BM = 128, BN = 64, BK = 16;
    __shared__ float As[BK][BM + 4];
    __shared__ float Bs[BK][BN];

    int t = threadIdx.x;
    int m0 = blockIdx.x * BM;
    int n0 = blockIdx.y * BN;
    int trow = (t >> 4) * 8;   // 0..120
    int tcol = (t & 15) * 4;   // 0..60

    int mmode = 0;
    if (AMODE != 0 || EPI == 1) mmode = g_mask_mode;

    ull acc[4][4];
#pragma unroll
    for (int p = 0; p < 4; p++)
#pragma unroll
        for (int j = 0; j < 4; j++) acc[p][j] = 0ull;

    int ar = t >> 2;          // 0..63
    int ak = (t & 3) * 4;     // 0,4,8,12
    int bn = t & 63;          // 0..63
    int bk = (t >> 6) * 4;    // 0,4,8,12

    for (int k0 = 0; k0 < Kdim; k0 += BK) {
        float4 v0 = load_a4<AMODE>(A, lda, m0 + ar, k0 + ak, center, maskp, ctxin, mmode);
        float4 v1 = load_a4<AMODE>(A, lda, m0 + ar + 64, k0 + ak, center, maskp, ctxin, mmode);
        As[ak + 0][ar] = v0.x; As[ak + 1][ar] = v0.y; As[ak + 2][ar] = v0.z; As[ak + 3][ar] = v0.w;
        As[ak + 0][ar + 64] = v1.x; As[ak + 1][ar + 64] = v1.y; As[ak + 2][ar + 64] = v1.z; As[ak + 3][ar + 64] = v1.w;

        float4 bv = *(const float4*)&Bw[(size_t)(n0 + bn) * ldb + k0 + bk];
        Bs[bk + 0][bn] = bv.x; Bs[bk + 1][bn] = bv.y; Bs[bk + 2][bn] = bv.z; Bs[bk + 3][bn] = bv.w;

        __syncthreads();
#pragma unroll
        for (int kk = 0; kk < BK; kk++) {
            ull a2[4];
#pragma unroll
            for (int p = 0; p < 4; p++)
                a2[p] = *(const ull*)&As[kk][trow + 2 * p];
            float4 b4 = *(const float4*)&Bs[kk][tcol];
            ull b2[4] = { pack2(b4.x, b4.x), pack2(b4.y, b4.y), pack2(b4.z, b4.z), pack2(b4.w, b4.w) };
#pragma unroll
            for (int p = 0; p < 4; p++)
#pragma unroll
                for (int j = 0; j < 4; j++)
                    FMA2(acc[p][j], a2[p], b2[j]);
        }
        __syncthreads();
    }

#pragma unroll
    for (int p = 0; p < 4; p++) {
        float lo[4], hi[4];
#pragma unroll
        for (int j = 0; j < 4; j++) unpack2(acc[p][j], lo[j], hi[j]);
        int r0 = m0 + trow + 2 * p;
        int cn = n0 + tcol;
        if (EPI == 0) {
            *(float4*)&C[(size_t)r0 * ldc + cn] = make_float4(lo[0], lo[1], lo[2], lo[3]);
            *(float4*)&C[(size_t)(r0 + 1) * ldc + cn] = make_float4(hi[0], hi[1], hi[2], hi[3]);
        } else {
            float fm0 = maskval(maskp, r0, mmode);
            float fm1 = maskval(maskp, r0 + 1, mmode);
            float4 cv0 = *(const float4*)&center[(size_t)r0 * 256 + cn];
            float4 cv1 = *(const float4*)&center[(size_t)(r0 + 1) * 256 + cn];
            float4 cx0 = *(const float4*)&ctxin[(size_t)r0 * 256 + cn];
            float4 cx1 = *(const float4*)&ctxin[(size_t)(r0 + 1) * 256 + cn];
            float4 o0, o1;
            o0.x = gatemix(lo[0], cv0.x * fm0, cx0.x);
            o0.y = gatemix(lo[1], cv0.y * fm0, cx0.y);
            o0.z = gatemix(lo[2], cv0.z * fm0, cx0.z);
            o0.w = gatemix(lo[3], cv0.w * fm0, cx0.w);
            o1.x = gatemix(hi[0], cv1.x * fm1, cx1.x);
            o1.y = gatemix(hi[1], cv1.y * fm1, cx1.y);
            o1.z = gatemix(hi[2], cv1.z * fm1, cx1.z);
            o1.w = gatemix(hi[3], cv1.w * fm1, cx1.w);
            *(float4*)&C[(size_t)r0 * ldc + cn] = o0;
            *(float4*)&C[(size_t)(r0 + 1) * ldc + cn] = o1;
        }
    }
}

// ---------------- GEMM entry kernels ----------------
__global__ void __launch_bounds__(256) k_gemm_q(const float* __restrict__ center,
                                                const float* __restrict__ Wq,
                                                const void* __restrict__ mask) {
    gemm_body<1, 0>(nullptr, 0, Wq, 256, g_Q, 128, 256, center, mask, nullptr);
}
__global__ void __launch_bounds__(256) k_gemm_u(int h) {
    gemm_body<0, 0>(g_Q + h * 64, 128, g_WkT + h * 16384, 64, g_U + h * 256, 512, 64,
                    nullptr, nullptr, nullptr);
}
__global__ void __launch_bounds__(256) k_gemm_ctx(const float* __restrict__ Wproj) {
    gemm_body<0, 0>(g_CTX, 512, Wproj, 512, g_CONTEXT, 256, 512, nullptr, nullptr, nullptr);
}
__global__ void __launch_bounds__(256) k_gemm_gate(const float* __restrict__ Wgate,
                                                   const float* __restrict__ center,
                                                   const void* __restrict__ mask,
                                                   float* __restrict__ out) {
    gemm_body<2, 1>(nullptr, 0, Wgate, 512, out, 256, 512, center, mask, g_CONTEXT);
}

// ---------------- attention: scores + softmax + context (DRAM-bound) ----------------
__global__ void __launch_bounds__(128) k_attn(const float* __restrict__ neigh,
                                              const float* __restrict__ conf) {
    __shared__ float sN[NK * 256];   // 16KB
    __shared__ float sU[512];
    __shared__ float sS[32];

    int b = blockIdx.x;
    int t = threadIdx.x;

    const float4* n4 = (const float4*)(neigh + (size_t)b * (NK * 256));
    float4* s4 = (float4*)sN;
#pragma unroll
    for (int i = 0; i < 8; i++) s4[t + i * 128] = n4[t + i * 128];
    ((float4*)sU)[t] = ((const float4*)(g_U + (size_t)b * 512))[t];
    __syncthreads();

    // scores: 32 (h,k) pairs, 4 lanes each
    {
        int p = t >> 2;
        int h = p >> 4;
        int k = p & 15;
        int l = t & 3;
        const float* u = sU + h * 256;
        const float* n = sN + k * 256;
        float s = 0.0f;
#pragma unroll 8
        for (int c = l; c < 256; c += 4) s += u[c] * n[c];
        s += __shfl_xor_sync(0xffffffffu, s, 1);
        s += __shfl_xor_sync(0xffffffffu, s, 2);
        if (l == 0) sS[p] = s * SCALE + logf(fmaxf(conf[(size_t)b * NK + k], 1e-8f));
    }
    __syncthreads();

    // softmax + ctx: thread t computes cols (t, t+128) for both heads
#pragma unroll
    for (int h = 0; h < 2; h++) {
        float m = -1e30f;
#pragma unroll
        for (int k = 0; k < NK; k++) m = fmaxf(m, sS[h * 16 + k]);
        float ws = 0.0f, c0 = 0.0f, c1 = 0.0f;
#pragma unroll
        for (int k = 0; k < NK; k++) {
            float w = expf(sS[h * 16 + k] - m);
            ws += w;
            c0 += w * sN[k * 256 + t];
            c1 += w * sN[k * 256 + t + 128];
        }
        float inv = 1.0f / ws;
        g_CTX[(size_t)b * 512 + h * 256 + t] = c0 * inv;
        g_CTX[(size_t)b * 512 + h * 256 + t + 128] = c1 * inv;
    }
}

// ---------------- launch ----------------
extern "C" void kernel_launch(void* const* d_in, const int* in_sizes, int n_in,
                              void* d_out, int out_size) {
    const float* center = (const float*)d_in[0];
    const float* neigh  = (const float*)d_in[1];
    const float* conf   = (const float*)d_in[2];
    const void*  mask   = d_in[3];
    const float* Wq     = (const float*)d_in[4];
    const float* Wk     = (const float*)d_in[5];
    const float* Wproj  = (const float*)d_in[6];
    const float* Wgate  = (const float*)d_in[7];
    float* out = (float*)d_out;

    k_detect_mask<<<1, 32>>>((const unsigned int*)mask);
    k_prep_wkt<<<128, 256>>>(Wk);

    k_gemm_q<<<dim3(NB / 128, 2), 256>>>(center, Wq, mask);
    k_gemm_u<<<dim3(NB / 128, 4), 256>>>(0);
    k_gemm_u<<<dim3(NB / 128, 4), 256>>>(1);

    k_attn<<<NB, 128>>>(neigh, conf);

    k_gemm_ctx<<<dim3(NB / 128, 4), 256>>>(Wproj);
    k_gemm_gate<<<dim3(NB / 128, 4), 256>>>(Wgate, center, mask, out);
}

// round 3
// speedup vs baseline: 1.1760x; 1.1755x over previous
#include <cuda_runtime.h>
#include <cuda_bf16.h>
#include <math.h>

typedef unsigned int u32;

#define NB 65536
#define NK 16
#define SCALE 0.125f

// ---------------- scratch (device globals; no allocation APIs) ----------------
__device__ float g_U[(size_t)NB * 512];        // [B, H*D] 128MB
__device__ float g_CTX[(size_t)NB * 512];      // [B, H*D] 128MB
__device__ float g_CONTEXT[(size_t)NB * 256];  // [B, D]    64MB
__device__ float g_M[512 * 256];               // fused Wk^T·Wq  [h*256+c][d]
__device__ int   g_mask_mode;                  // 0=u8, 1=i32, 2=f32

// ---------------- valid_mask dtype probe ----------------
__global__ void k_detect_mask(const unsigned int* __restrict__ w) {
    if (threadIdx.x == 0 && blockIdx.x == 0) {
        int f32like = 1, i32like = 1;
        for (int i = 0; i < 64; i++) {
            unsigned v = w[i];
            if (v != 0u && v != 0x3F800000u) f32like = 0;
            if (v > 1u) i32like = 0;
        }
        g_mask_mode = f32like ? 2 : (i32like ? 1 : 0);
    }
}

__device__ __forceinline__ float maskval(const void* p, int b, int mode) {
    if (mode == 0) return ((const unsigned char*)p)[b] ? 1.0f : 0.0f;
    if (mode == 1) return ((const int*)p)[b] ? 1.0f : 0.0f;
    return (((const float*)p)[b] != 0.0f) ? 1.0f : 0.0f;
}

// ---------------- precompute M_h = Wk_h^T @ Wq_h : g_M[h*256+c][d] ----------------
__global__ void __launch_bounds__(256) k_prep_M(const float* __restrict__ Wq,
                                                const float* __restrict__ Wk) {
    __shared__ float sWk[64][8];
    int bx = blockIdx.x;           // 64 blocks
    int h = bx >> 5;
    int c0 = (bx & 31) * 8;
    int t = threadIdx.x;
    for (int i = t; i < 64 * 8; i += 256) {
        int a = i >> 3, j = i & 7;
        sWk[a][j] = Wk[h * 16384 + a * 256 + c0 + j];
    }
    __syncthreads();
    int d = t;
    float acc[8] = {0, 0, 0, 0, 0, 0, 0, 0};
    for (int a = 0; a < 64; a++) {
        float w = Wq[h * 16384 + a * 256 + d];
#pragma unroll
        for (int j = 0; j < 8; j++) acc[j] += sWk[a][j] * w;
    }
#pragma unroll
    for (int j = 0; j < 8; j++)
        g_M[(h * 256 + c0 + j) * 256 + d] = acc[j];
}

// ---------------- bf16 helpers ----------------
__device__ __forceinline__ u32 bf2(float lo, float hi) {
    u32 r;
    asm("cvt.rn.bf16x2.f32 %0, %2, %1;" : "=r"(r) : "f"(lo), "f"(hi));
    return r;
}

#define MMA_BF16(acc, a, b)                                                     \
    asm volatile(                                                               \
        "mma.sync.aligned.m16n8k16.row.col.f32.bf16.bf16.f32 "                  \
        "{%0,%1,%2,%3},{%4,%5,%6,%7},{%8,%9},{%0,%1,%2,%3};"                    \
        : "+f"((acc)[0]), "+f"((acc)[1]), "+f"((acc)[2]), "+f"((acc)[3])        \
        : "r"((a)[0]), "r"((a)[1]), "r"((a)[2]), "r"((a)[3]),                   \
          "r"((b)[0]), "r"((b)[1]))

__device__ __forceinline__ float gatemix(float x, float cv, float cx) {
    float g = 1.0f / (1.0f + expf(-x));
    return g * cv + (1.0f - g) * cx;
}

// ---------------- tensor-core GEMM: C[M,N] = A[M,K] @ Bw[N,K]^T ----------------
// BM=128, BN=128, BK=32. 256 threads = 8 warps (2m x 4n), warp tile 64x32.
// fp32 accuracy via 2-term bf16 split: Ah*Bh + Al*Bh + Ah*Bl.
// AMODE 0: plain A; 1: masked center (lda=256); 2: [masked center | g_CONTEXT] K=512.
// EPI 0: plain store; 1: sigmoid-gate mix epilogue.
template <int AMODE, int EPI>
__device__ __forceinline__ void gemm_mma(const float* __restrict__ A, int lda,
                                         const float* __restrict__ Bw, int ldb,
                                         float* __restrict__ C, int ldc, int Kdim,
                                         const float* __restrict__ center,
                                         const void* __restrict__ maskp,
                                         const float* __restrict__ ctxin) {
    // row stride 20 words (16 data + 4 pad) -> conflict-free fragment LDS
    __shared__ u32 sAh[128 * 20];
    __shared__ u32 sAl[128 * 20];
    __shared__ u32 sBh[128 * 20];
    __shared__ u32 sBl[128 * 20];

    int t = threadIdx.x;
    int warp = t >> 5, lane = t & 31;
    int g = lane >> 2, t4 = lane & 3;
    int warp_m = warp & 1, warp_n = warp >> 1;
    int m0 = blockIdx.x * 128, n0 = blockIdx.y * 128;
    int mmode = (AMODE != 0 || EPI == 1) ? g_mask_mode : 0;

    float acc[4][4][4];
#pragma unroll
    for (int mi = 0; mi < 4; mi++)
#pragma unroll
        for (int ni = 0; ni < 4; ni++)
#pragma unroll
            for (int e = 0; e < 4; e++) acc[mi][ni][e] = 0.0f;

    int lr = t >> 1;            // tile row 0..127
    int lhalf = t & 1;          // which 16-float half of BK=32
    int sbase = lr * 20 + lhalf * 8;

    for (int k0 = 0; k0 < Kdim; k0 += 32) {
        // ---- A tile: 128 x 32 fp32 -> split bf16 ----
        {
            int row = m0 + lr;
            int kg = k0 + lhalf * 16;
            const float* src;
            float fm = 1.0f;
            if (AMODE == 0) {
                src = &A[(size_t)row * lda + kg];
            } else if (AMODE == 1) {
                src = &center[(size_t)row * 256 + kg];
                fm = maskval(maskp, row, mmode);
            } else {
                if (kg < 256) {
                    src = &center[(size_t)row * 256 + kg];
                    fm = maskval(maskp, row, mmode);
                } else {
                    src = &ctxin[(size_t)row * 256 + (kg - 256)];
                }
            }
            float av[16];
#pragma unroll
            for (int i = 0; i < 4; i++) {
                float4 v = ((const float4*)src)[i];
                av[4 * i + 0] = v.x * fm; av[4 * i + 1] = v.y * fm;
                av[4 * i + 2] = v.z * fm; av[4 * i + 3] = v.w * fm;
            }
#pragma unroll
            for (int i = 0; i < 8; i++) {
                float x0 = av[2 * i], x1 = av[2 * i + 1];
                __nv_bfloat16 h0 = __float2bfloat16(x0), h1 = __float2bfloat16(x1);
                float r0 = x0 - __bfloat162float(h0);
                float r1 = x1 - __bfloat162float(h1);
                __nv_bfloat162 hp; hp.x = h0; hp.y = h1;
                sAh[sbase + i] = *(u32*)&hp;
                sAl[sbase + i] = bf2(r0, r1);
            }
        }
        // ---- B tile: 128 x 32 fp32 (weights, [N][K] row-major) ----
        {
            const float* src = &Bw[(size_t)(n0 + lr) * ldb + k0 + lhalf * 16];
            float bv[16];
#pragma unroll
            for (int i = 0; i < 4; i++) {
                float4 v = ((const float4*)src)[i];
                bv[4 * i + 0] = v.x; bv[4 * i + 1] = v.y;
                bv[4 * i + 2] = v.z; bv[4 * i + 3] = v.w;
            }
#pragma unroll
            for (int i = 0; i < 8; i++) {
                float x0 = bv[2 * i], x1 = bv[2 * i + 1];
                __nv_bfloat16 h0 = __float2bfloat16(x0), h1 = __float2bfloat16(x1);
                float r0 = x0 - __bfloat162float(h0);
                float r1 = x1 - __bfloat162float(h1);
                __nv_bfloat162 hp; hp.x = h0; hp.y = h1;
                sBh[sbase + i] = *(u32*)&hp;
                sBl[sbase + i] = bf2(r0, r1);
            }
        }
        __syncthreads();

#pragma unroll
        for (int kk = 0; kk < 2; kk++) {
            u32 ah[4][4], al[4][4], bh[4][2], bl[4][2];
#pragma unroll
            for (int mi = 0; mi < 4; mi++) {
                int rm = warp_m * 64 + mi * 16;
                int w0 = (rm + g) * 20 + kk * 8 + t4;
                int w1 = (rm + g + 8) * 20 + kk * 8 + t4;
                ah[mi][0] = sAh[w0]; ah[mi][1] = sAh[w1];
                ah[mi][2] = sAh[w0 + 4]; ah[mi][3] = sAh[w1 + 4];
                al[mi][0] = sAl[w0]; al[mi][1] = sAl[w1];
                al[mi][2] = sAl[w0 + 4]; al[mi][3] = sAl[w1 + 4];
            }
#pragma unroll
            for (int ni = 0; ni < 4; ni++) {
                int w0 = (warp_n * 32 + ni * 8 + g) * 20 + kk * 8 + t4;
                bh[ni][0] = sBh[w0]; bh[ni][1] = sBh[w0 + 4];
                bl[ni][0] = sBl[w0]; bl[ni][1] = sBl[w0 + 4];
            }
#pragma unroll
            for (int mi = 0; mi < 4; mi++)
#pragma unroll
                for (int ni = 0; ni < 4; ni++) {
                    MMA_BF16(acc[mi][ni], ah[mi], bh[ni]);
                    MMA_BF16(acc[mi][ni], al[mi], bh[ni]);
                    MMA_BF16(acc[mi][ni], ah[mi], bl[ni]);
                }
        }
        __syncthreads();
    }

    // ---- epilogue ----
#pragma unroll
    for (int mi = 0; mi < 4; mi++) {
        int r0 = m0 + warp_m * 64 + mi * 16 + g;
#pragma unroll
        for (int ni = 0; ni < 4; ni++) {
            int cn = n0 + warp_n * 32 + ni * 8 + 2 * t4;
            float* a = acc[mi][ni];
            if (EPI == 0) {
                *(float2*)&C[(size_t)r0 * ldc + cn] = make_float2(a[0], a[1]);
                *(float2*)&C[(size_t)(r0 + 8) * ldc + cn] = make_float2(a[2], a[3]);
            } else {
                float fm0 = maskval(maskp, r0, mmode);
                float fm1 = maskval(maskp, r0 + 8, mmode);
                float2 cv0 = *(const float2*)&center[(size_t)r0 * 256 + cn];
                float2 cv1 = *(const float2*)&center[(size_t)(r0 + 8) * 256 + cn];
                float2 cx0 = *(const float2*)&ctxin[(size_t)r0 * 256 + cn];
                float2 cx1 = *(const float2*)&ctxin[(size_t)(r0 + 8) * 256 + cn];
                float2 o0, o1;
                o0.x = gatemix(a[0], cv0.x * fm0, cx0.x);
                o0.y = gatemix(a[1], cv0.y * fm0, cx0.y);
                o1.x = gatemix(a[2], cv1.x * fm1, cx1.x);
                o1.y = gatemix(a[3], cv1.y * fm1, cx1.y);
                *(float2*)&C[(size_t)r0 * ldc + cn] = o0;
                *(float2*)&C[(size_t)(r0 + 8) * ldc + cn] = o1;
            }
        }
    }
}

// ---------------- GEMM entry kernels ----------------
__global__ void __launch_bounds__(256) k_gemm_u(const float* __restrict__ center,
                                                const void* __restrict__ mask) {
    // U[B,512] = center_masked[B,256] @ g_M[512,256]^T
    gemm_mma<1, 0>(nullptr, 0, g_M, 256, g_U, 512, 256, center, mask, nullptr);
}
__global__ void __launch_bounds__(256) k_gemm_ctx(const float* __restrict__ Wproj) {
    gemm_mma<0, 0>(g_CTX, 512, Wproj, 512, g_CONTEXT, 256, 512, nullptr, nullptr, nullptr);
}
__global__ void __launch_bounds__(256) k_gemm_gate(const float* __restrict__ Wgate,
                                                   const float* __restrict__ center,
                                                   const void* __restrict__ mask,
                                                   float* __restrict__ out) {
    gemm_mma<2, 1>(nullptr, 0, Wgate, 512, out, 256, 512, center, mask, g_CONTEXT);
}

// ---------------- attention: scores + softmax + context (DRAM-bound) ----------------
__global__ void __launch_bounds__(128) k_attn(const float* __restrict__ neigh,
                                              const float* __restrict__ conf) {
    __shared__ float sN[NK * 256];   // 16KB
    __shared__ float sU[512];
    __shared__ float sS[32];

    int b = blockIdx.x;
    int t = threadIdx.x;

    const float4* n4 = (const float4*)(neigh + (size_t)b * (NK * 256));
    float4* s4 = (float4*)sN;
#pragma unroll
    for (int i = 0; i < 8; i++) s4[t + i * 128] = n4[t + i * 128];
    ((float4*)sU)[t] = ((const float4*)(g_U + (size_t)b * 512))[t];
    __syncthreads();

    // scores: 32 (h,k) pairs, 4 lanes each
    {
        int p = t >> 2;
        int h = p >> 4;
        int k = p & 15;
        int l = t & 3;
        const float* u = sU + h * 256;
        const float* n = sN + k * 256;
        float s = 0.0f;
#pragma unroll 8
        for (int c = l; c < 256; c += 4) s += u[c] * n[c];
        s += __shfl_xor_sync(0xffffffffu, s, 1);
        s += __shfl_xor_sync(0xffffffffu, s, 2);
        if (l == 0) sS[p] = s * SCALE + logf(fmaxf(conf[(size_t)b * NK + k], 1e-8f));
    }
    __syncthreads();

    // softmax + ctx: thread t computes cols (t, t+128) for both heads
#pragma unroll
    for (int h = 0; h < 2; h++) {
        float m = -1e30f;
#pragma unroll
        for (int k = 0; k < NK; k++) m = fmaxf(m, sS[h * 16 + k]);
        float ws = 0.0f, c0 = 0.0f, c1 = 0.0f;
#pragma unroll
        for (int k = 0; k < NK; k++) {
            float w = expf(sS[h * 16 + k] - m);
            ws += w;
            c0 += w * sN[k * 256 + t];
            c1 += w * sN[k * 256 + t + 128];
        }
        float inv = 1.0f / ws;
        g_CTX[(size_t)b * 512 + h * 256 + t] = c0 * inv;
        g_CTX[(size_t)b * 512 + h * 256 + t + 128] = c1 * inv;
    }
}

// ---------------- launch ----------------
extern "C" void kernel_launch(void* const* d_in, const int* in_sizes, int n_in,
                              void* d_out, int out_size) {
    const float* center = (const float*)d_in[0];
    const float* neigh  = (const float*)d_in[1];
    const float* conf   = (const float*)d_in[2];
    const void*  mask   = d_in[3];
    const float* Wq     = (const float*)d_in[4];
    const float* Wk     = (const float*)d_in[5];
    const float* Wproj  = (const float*)d_in[6];
    const float* Wgate  = (const float*)d_in[7];
    float* out = (float*)d_out;

    k_detect_mask<<<1, 32>>>((const unsigned int*)mask);
    k_prep_M<<<64, 256>>>(Wq, Wk);

    k_gemm_u<<<dim3(NB / 128, 4), 256>>>(center, mask);

    k_attn<<<NB, 128>>>(neigh, conf);

    k_gemm_ctx<<<dim3(NB / 128, 2), 256>>>(Wproj);
    k_gemm_gate<<<dim3(NB / 128, 2), 256>>>(Wgate, center, mask, out);
}